// round 1
// baseline (speedup 1.0000x reference)
#include <cuda_runtime.h>
#include <cuda_fp16.h>
#include <math.h>

#define NN 4096
#define DD 64
#define TS 128           // DTW tile size
#define NT (NN / TS)     // 32 tiles per side
#define BIGF 1e30f

// Scratch (static device globals — no runtime allocation)
__device__ __half g_cost[(size_t)NN * NN];   // 32 MB, fp16 costs
__device__ float  g_nx[NN];
__device__ float  g_ny[NN];
__device__ float  g_HB[NT * NN];   // bottom-row D of tile-row ti, indexed [ti*NN + gj]
__device__ float  g_VB[NT * NN];   // right-col D of tile-col tj, indexed [tj*NN + gi]

// ---------------------------------------------------------------------------
// Phase 0: squared norms of rows of x and y
// ---------------------------------------------------------------------------
__global__ void norms_kernel(const float* __restrict__ x, const float* __restrict__ y) {
    int i = blockIdx.x * blockDim.x + threadIdx.x;
    if (i < NN) {
        const float* p = x + (size_t)i * DD;
        float s = 0.f;
        #pragma unroll
        for (int k = 0; k < DD; k++) s += p[k] * p[k];
        g_nx[i] = s;
    } else if (i < 2 * NN) {
        int j = i - NN;
        const float* p = y + (size_t)j * DD;
        float s = 0.f;
        #pragma unroll
        for (int k = 0; k < DD; k++) s += p[k] * p[k];
        g_ny[j] = s;
    }
}

// ---------------------------------------------------------------------------
// Phase 1: cost matrix c[i][j] = sqrt(max(|x_i|^2 + |y_j|^2 - 2 x_i.y_j, 1e-12))
// 64x64 tile per block, 16x16 threads, 4x4 per thread, fp32 compute, fp16 store.
// ---------------------------------------------------------------------------
__global__ void cost_kernel(const float* __restrict__ x, const float* __restrict__ y) {
    __shared__ float xs[64][DD + 1];
    __shared__ float ys[64][DD + 1];

    int I0 = blockIdx.y * 64;
    int J0 = blockIdx.x * 64;
    int tid = threadIdx.y * 16 + threadIdx.x;   // 0..255

    // cooperative load of both 64x64 fp32 tiles (coalesced along k)
    for (int t = tid; t < 64 * DD; t += 256) {
        int r = t >> 6;          // /64
        int k = t & 63;          // %64
        xs[r][k] = x[(size_t)(I0 + r) * DD + k];
        ys[r][k] = y[(size_t)(J0 + r) * DD + k];
    }
    __syncthreads();

    float acc[4][4];
    #pragma unroll
    for (int a = 0; a < 4; a++)
        #pragma unroll
        for (int b = 0; b < 4; b++) acc[a][b] = 0.f;

    int r0 = threadIdx.y * 4;
    int c0 = threadIdx.x * 4;

    #pragma unroll 8
    for (int k = 0; k < DD; k++) {
        float ra[4], rb[4];
        #pragma unroll
        for (int a = 0; a < 4; a++) ra[a] = xs[r0 + a][k];
        #pragma unroll
        for (int b = 0; b < 4; b++) rb[b] = ys[c0 + b][k];
        #pragma unroll
        for (int a = 0; a < 4; a++)
            #pragma unroll
            for (int b = 0; b < 4; b++) acc[a][b] = fmaf(ra[a], rb[b], acc[a][b]);
    }

    #pragma unroll
    for (int a = 0; a < 4; a++) {
        float nx = g_nx[I0 + r0 + a];
        #pragma unroll
        for (int b = 0; b < 4; b++) {
            float ny = g_ny[J0 + c0 + b];
            float sq = nx + ny - 2.0f * acc[a][b];
            float c  = sqrtf(fmaxf(sq, 1e-12f));
            g_cost[(size_t)(I0 + r0 + a) * NN + (J0 + c0 + b)] = __float2half(c);
        }
    }
}

// ---------------------------------------------------------------------------
// Phase 2: DTW wavefront over 128x128 tiles, launched per tile-diagonal.
// Thread j owns column j of the tile; skewed stepping: at step s it computes
// row i = s - j. Its "up" value lives in a register; left/diag come from a
// 3-buffer rotating shared array (one __syncthreads per step, no RW hazard).
// Recurrence (symmetric2): D = min(diag + 2c, up + c, left + c).
// ---------------------------------------------------------------------------
__global__ void dtw_kernel(int diag, float* __restrict__ out) {
    int tmin = diag - (NT - 1); if (tmin < 0) tmin = 0;
    int ti = tmin + blockIdx.x;
    int tj = diag - ti;
    int gi0 = ti * TS;
    int gj0 = tj * TS;
    int tid = threadIdx.x;   // 0..127

    __shared__ __half sc[TS][TS];     // 32 KB cost tile
    __shared__ float  sTop[TS + 1];   // sTop[0] = corner, sTop[j+1] = top row
    __shared__ float  sL[TS];         // left boundary column
    __shared__ float  sD[3][TS];      // rotating wavefront buffers

    // stage cost tile (coalesced: consecutive tid -> consecutive addresses)
    #pragma unroll 4
    for (int i = 0; i < TS; i++)
        sc[i][tid] = g_cost[(size_t)(gi0 + i) * NN + gj0 + tid];

    sTop[tid + 1] = (ti == 0) ? BIGF : g_HB[(ti - 1) * NN + gj0 + tid];
    sL[tid]       = (tj == 0) ? BIGF : g_VB[(tj - 1) * NN + gi0 + tid];
    if (tid == 0) {
        if (ti == 0 && tj == 0)
            sTop[0] = -__half2float(g_cost[0]);    // virtual corner: D[0,0]=c00
        else if (ti == 0 || tj == 0)
            sTop[0] = BIGF;
        else
            sTop[0] = g_HB[(ti - 1) * NN + gj0 - 1];
    }
    __syncthreads();

    float prev = 0.f;   // D[i-1][my col]; valid from the first active step on
    for (int s = 0; s < 2 * TS - 1; s++) {
        int i = s - tid;
        if (i >= 0 && i < TS) {
            float c = __half2float(sc[i][tid]);
            float up, dg, lf;
            if (i == 0) {
                up = sTop[tid + 1];
                dg = sTop[tid];
                lf = (tid == 0) ? sL[0] : sD[(s + 2) % 3][tid - 1];
            } else {
                up = prev;
                if (tid == 0) {
                    dg = sL[i - 1];
                    lf = sL[i];
                } else {
                    dg = sD[(s + 1) % 3][tid - 1];   // step s-2 value of thread j-1
                    lf = sD[(s + 2) % 3][tid - 1];   // step s-1 value of thread j-1
                }
            }
            float v = fminf(fminf(dg + 2.0f * c, up + c), lf + c);
            prev = v;
            sD[s % 3][tid] = v;
            if (i == TS - 1)  g_HB[ti * NN + gj0 + tid] = v;
            if (tid == TS - 1) g_VB[tj * NN + gi0 + i]  = v;
        }
        __syncthreads();
    }

    if (ti == NT - 1 && tj == NT - 1 && tid == TS - 1)
        out[0] = prev;   // D[N-1][M-1]
}

// ---------------------------------------------------------------------------
extern "C" void kernel_launch(void* const* d_in, const int* in_sizes, int n_in,
                              void* d_out, int out_size) {
    const float* x = (const float*)d_in[0];
    const float* y = (const float*)d_in[1];
    float* out = (float*)d_out;

    norms_kernel<<<(2 * NN + 511) / 512, 512>>>(x, y);
    cost_kernel<<<dim3(NN / 64, NN / 64), dim3(16, 16)>>>(x, y);

    for (int d = 0; d < 2 * NT - 1; d++) {
        int tmin = d - (NT - 1); if (tmin < 0) tmin = 0;
        int tmax = (d < NT - 1) ? d : NT - 1;
        int nb = tmax - tmin + 1;
        dtw_kernel<<<nb, TS>>>(d, out);
    }
}

// round 2
// speedup vs baseline: 3.4434x; 3.4434x over previous
#include <cuda_runtime.h>
#include <cuda_fp16.h>
#include <math.h>

#define NN 4096
#define DD 64
#define BIGF 1e30f
#define NWARP 64          // 64 strips of 64 columns
#define PF 8              // cost prefetch distance (steps)
#define STEPS 4128        // >= 4096+31, multiple of PF
#define FULLM 0xffffffffu

// Static device scratch (no runtime allocation)
__device__ __half g_cost[(size_t)NN * NN];   // 32 MB fp16 cost matrix
__device__ float  g_nx[NN];
__device__ float  g_ny[NN];
__device__ float  g_bnd[NWARP * NN];         // right-column boundary per strip
__device__ int    g_flag[NWARP];             // rows-completed flag per strip

// ---------------------------------------------------------------------------
__global__ void reset_kernel() {
    if (threadIdx.x < NWARP) g_flag[threadIdx.x] = 0;
}

// ---------------------------------------------------------------------------
__global__ void norms_kernel(const float* __restrict__ x, const float* __restrict__ y) {
    int i = blockIdx.x * blockDim.x + threadIdx.x;
    if (i < NN) {
        const float* p = x + (size_t)i * DD;
        float s = 0.f;
        #pragma unroll
        for (int k = 0; k < DD; k++) s += p[k] * p[k];
        g_nx[i] = s;
    } else if (i < 2 * NN) {
        int j = i - NN;
        const float* p = y + (size_t)j * DD;
        float s = 0.f;
        #pragma unroll
        for (int k = 0; k < DD; k++) s += p[k] * p[k];
        g_ny[j] = s;
    }
}

// ---------------------------------------------------------------------------
// Cost matrix: c[i][j] = sqrt(max(|x_i|^2+|y_j|^2-2 x_i.y_j, 1e-12)), fp16 store.
// ---------------------------------------------------------------------------
__global__ void cost_kernel(const float* __restrict__ x, const float* __restrict__ y) {
    __shared__ float xs[64][DD + 1];
    __shared__ float ys[64][DD + 1];

    int I0 = blockIdx.y * 64;
    int J0 = blockIdx.x * 64;
    int tid = threadIdx.y * 16 + threadIdx.x;

    for (int t = tid; t < 64 * DD; t += 256) {
        int r = t >> 6;
        int k = t & 63;
        xs[r][k] = x[(size_t)(I0 + r) * DD + k];
        ys[r][k] = y[(size_t)(J0 + r) * DD + k];
    }
    __syncthreads();

    float acc[4][4];
    #pragma unroll
    for (int a = 0; a < 4; a++)
        #pragma unroll
        for (int b = 0; b < 4; b++) acc[a][b] = 0.f;

    int r0 = threadIdx.y * 4;
    int c0 = threadIdx.x * 4;

    #pragma unroll 8
    for (int k = 0; k < DD; k++) {
        float ra[4], rb[4];
        #pragma unroll
        for (int a = 0; a < 4; a++) ra[a] = xs[r0 + a][k];
        #pragma unroll
        for (int b = 0; b < 4; b++) rb[b] = ys[c0 + b][k];
        #pragma unroll
        for (int a = 0; a < 4; a++)
            #pragma unroll
            for (int b = 0; b < 4; b++) acc[a][b] = fmaf(ra[a], rb[b], acc[a][b]);
    }

    #pragma unroll
    for (int a = 0; a < 4; a++) {
        float nx = g_nx[I0 + r0 + a];
        #pragma unroll
        for (int b = 0; b < 4; b++) {
            float ny = g_ny[J0 + c0 + b];
            float sq = nx + ny - 2.0f * acc[a][b];
            float c  = sqrtf(fmaxf(sq, 1e-12f));
            g_cost[(size_t)(I0 + r0 + a) * NN + (J0 + c0 + b)] = __float2half(c);
        }
    }
}

// ---------------------------------------------------------------------------
// Persistent DTW wavefront: one warp per 64-column strip, lane owns 2 columns.
// Lane l at step s computes row r = s - l for cols (base+2l, base+2l+1).
// Neighbor values via __shfl_up_sync; cross-strip boundary via global buffer
// with chunked flag handoff (C=32 rows). No __syncthreads anywhere.
// ---------------------------------------------------------------------------
__global__ void __launch_bounds__(32, 1) dtw_kernel(float* __restrict__ out) {
    const int w    = blockIdx.x;            // strip id 0..63
    const int lane = threadIdx.x;           // 0..31
    const int colbase = w * 64 + 2 * lane;  // my even column
    const __half2* cptr = (const __half2*)g_cost;
    const int cidx = colbase >> 1;

    // state: after step s, v1c0 = D[s-l][c0], v1c1 = D[s-l][c1], v2c1 = D[s-l-1][c1]
    float v1c0 = BIGF, v1c1 = BIGF, v2c1 = BIGF;
    float prev0 = BIGF;                     // lane0: D[r-1][base-1]
    float negc = 0.f;
    if (w == 0 && lane == 0)
        negc = -__half2float(((const __half*)g_cost)[0]);  // virtual corner

    float bval = BIGF;                      // my slot of current boundary chunk
    const volatile int*   flagp = (w > 0) ? (const volatile int*)&g_flag[w - 1] : (const volatile int*)0;
    const volatile float* bndp  = (w > 0) ? (const volatile float*)&g_bnd[(w - 1) * NN] : (const volatile float*)0;
    float* mybnd = &g_bnd[w * NN];

    // prime cost prefetch ring
    __half2 cp[PF];
    #pragma unroll
    for (int k = 0; k < PF; k++) {
        int r = k - lane;
        r = r < 0 ? 0 : (r > NN - 1 ? NN - 1 : r);
        cp[k] = cptr[(size_t)r * (NN / 2) + cidx];
    }

    for (int s = 0; s < STEPS; s += PF) {
        #pragma unroll
        for (int k = 0; k < PF; k++) {
            const int ss = s + k;

            // chunk handoff: once per 32 steps, wait for left strip and load chunk
            if (w > 0 && (ss & 31) == 0 && ss < NN) {
                while (*flagp < ss + 32) { }
                bval = bndp[ss + lane];
            }

            // neighbor exchange (warp-uniform, unconditional)
            float lfs = __shfl_up_sync(FULLM, v1c1, 1);
            float dgs = __shfl_up_sync(FULLM, v2c1, 1);
            float bb = BIGF;
            if (w > 0) bb = __shfl_sync(FULLM, bval, ss & 31);

            float lfv = lfs, dgv = dgs;
            if (lane == 0) {
                if (w > 0) { lfv = bb; dgv = prev0; prev0 = bb; }
                else       { lfv = BIGF; dgv = (ss == 0) ? negc : BIGF; }
            }

            const int  r   = ss - lane;
            const bool act = (r >= 0) && (r < NN);

            float2 cc = __half22float2(cp[k]);
            const float c0 = cc.x, c1 = cc.y;

            // cell 0 (even column)
            float a0 = fmaf(2.0f, c0, dgv);
            float b0 = v1c0 + c0;
            float n0 = fminf(fminf(a0, b0), lfv + c0);
            // cell 1 (odd column) — diag is old v1c0, left is n0
            float a1 = fmaf(2.0f, c1, v1c0);
            float b1 = v1c1 + c1;
            float n1 = fminf(fminf(a1, b1), n0 + c1);

            // prefetch cost for step ss+PF (issued off the dependency chain)
            int rl = ss + PF - lane;
            rl = rl < 0 ? 0 : (rl > NN - 1 ? NN - 1 : rl);
            __half2 nxt = cptr[(size_t)rl * (NN / 2) + cidx];

            if (act) {
                v2c1 = v1c1;
                v1c1 = n1;
                v1c0 = n0;
                if (lane == 31) {
                    mybnd[r] = n1;
                    if ((r & 31) == 31) {
                        __threadfence();
                        atomicExch(&g_flag[w], r + 1);
                    }
                    if (w == NWARP - 1 && r == NN - 1) out[0] = n1;
                }
            }
            cp[k] = nxt;
        }
    }
}

// ---------------------------------------------------------------------------
extern "C" void kernel_launch(void* const* d_in, const int* in_sizes, int n_in,
                              void* d_out, int out_size) {
    const float* x = (const float*)d_in[0];
    const float* y = (const float*)d_in[1];
    float* out = (float*)d_out;

    reset_kernel<<<1, 64>>>();
    norms_kernel<<<(2 * NN + 511) / 512, 512>>>(x, y);
    cost_kernel<<<dim3(NN / 64, NN / 64), dim3(16, 16)>>>(x, y);
    dtw_kernel<<<NWARP, 32>>>(out);
}